// round 11
// baseline (speedup 1.0000x reference)
#include <cuda_runtime.h>

#define HH 64
#define WW 64
#define HWSZ 4096          // 64*64
#define CH 64
#define QCH 32
#define BATCH 4

typedef unsigned long long u64;

// ---------------- scratch (device globals; no allocation allowed) -------------
__device__ float g_v1[BATCH*CH*HWSZ];
__device__ float g_v [BATCH*CH*HWSZ];
__device__ float g_f1[BATCH*CH*HWSZ];
__device__ float g_f2[BATCH*CH*HWSZ];
__device__ float g_q [BATCH*QCH*HWSZ];
__device__ float g_k [BATCH*QCH*HWSZ];
__device__ float g_invq[BATCH*HWSZ];
__device__ float g_invk[BATCH*HWSZ];
__device__ u64   g_pk[BATCH*HWSZ];                 // packed (fkey(max)<<32)|~argmax
__device__ float g_E[(size_t)BATCH*HWSZ*HWSZ];     // x-pass box-summed dots (fp32)

// ---------------- helpers -----------------------------------------------------
__device__ __forceinline__ unsigned fkey(float f) {
    unsigned u = __float_as_uint(f);
    return (u & 0x80000000u) ? ~u : (u | 0x80000000u);
}
__device__ __forceinline__ u64 pack2(float lo, float hi) {
    u64 r;
    asm("mov.b64 %0, {%1, %2};" : "=l"(r)
        : "r"(__float_as_uint(lo)), "r"(__float_as_uint(hi)));
    return r;
}
__device__ __forceinline__ void fma2(u64 &d, u64 a, u64 b) {
    asm("fma.rn.f32x2 %0, %1, %2, %0;" : "+l"(d) : "l"(a), "l"(b));
}
__device__ __forceinline__ float lo32(u64 v) { return __uint_as_float((unsigned)v); }
__device__ __forceinline__ float hi32(u64 v) { return __uint_as_float((unsigned)(v >> 32)); }
__device__ __forceinline__ u64 u64max_(u64 a, u64 b) { return a > b ? a : b; }

// ---------------- 3x3 same conv body, Cin=64, NCHW, f32x2 ---------------------
// block: 256 threads; spatial tile 32(h) x 16(w); each thread: 2 pixels x 8 oc.
__device__ __forceinline__ void conv_body(const float* __restrict__ in,
                                          const float* __restrict__ in2,
                                          const float* __restrict__ w,
                                          const float* __restrict__ bias,
                                          float* __restrict__ out,
                                          int oc0, int relu, int b, int Cout) {
    __shared__ float tile[16][34][18];   // [ci][y][x] halo tile
    __shared__ u64 ws2[16*9*4];          // [ci][tap][ocpair]  (8 oc = 4 pairs)

    const int tid = threadIdx.x;
    const int px = tid & 15, py = tid >> 4;        // py 0..15
    const int ty0 = (blockIdx.x >> 2) * 32;        // 2 vertical tiles
    const int tx0 = (blockIdx.x & 3) * 16;         // 4 horizontal tiles

    u64 acc0[4], acc1[4];
#pragma unroll
    for (int o = 0; o < 4; o++) { acc0[o] = 0ull; acc1[o] = 0ull; }

    const float* inb  = in  + (size_t)b * CH * HWSZ;
    const float* in2b = in2 ? in2 + (size_t)b * CH * HWSZ : nullptr;

    for (int c0 = 0; c0 < CH; c0 += 16) {
        // halo tile load: 16 ch x 34 x 18
        for (int idx = tid; idx < 16*34*18; idx += 256) {
            int ci  = idx / 612;
            int rem = idx - ci * 612;
            int yy  = rem / 18, xx = rem - yy * 18;
            int gy = ty0 + yy - 1, gx = tx0 + xx - 1;
            float val = 0.f;
            if (gy >= 0 && gy < HH && gx >= 0 && gx < WW) {
                size_t off = (size_t)(c0 + ci) * HWSZ + gy * WW + gx;
                val = inb[off];
                if (in2b) val += in2b[off];
            }
            tile[ci][yy][xx] = val;
        }
        // weight pairs: 16 ci x 9 taps x 4 ocpairs
        for (int idx = tid; idx < 16*9*4; idx += 256) {
            int o  = idx & 3;
            int tt = (idx >> 2) % 9;
            int ci = idx / 36;
            float w0 = w[((size_t)(oc0 + 2*o)     * CH + (c0 + ci)) * 9 + tt];
            float w1 = w[((size_t)(oc0 + 2*o + 1) * CH + (c0 + ci)) * 9 + tt];
            ws2[idx] = pack2(w0, w1);
        }
        __syncthreads();

#pragma unroll 2
        for (int ci = 0; ci < 16; ci++) {
#pragma unroll
            for (int t = 0; t < 9; t++) {
                const int dy = t / 3, dx = t - 3 * (t / 3);
                float xv0 = tile[ci][py + dy][px + dx];
                float xv1 = tile[ci][py + 16 + dy][px + dx];
                u64 x02 = pack2(xv0, xv0);
                u64 x12 = pack2(xv1, xv1);
                const u64* wp = &ws2[(ci * 9 + t) * 4];
#pragma unroll
                for (int o = 0; o < 4; o++) {
                    u64 wv = wp[o];
                    fma2(acc0[o], x02, wv);
                    fma2(acc1[o], x12, wv);
                }
            }
        }
        __syncthreads();
    }

    const int gx = tx0 + px;
    const int gy0 = ty0 + py, gy1 = ty0 + py + 16;
#pragma unroll
    for (int o = 0; o < 4; o++) {
        float bia0 = bias[oc0 + 2*o], bia1 = bias[oc0 + 2*o + 1];
        float a0 = lo32(acc0[o]) + bia0;
        float a1 = hi32(acc0[o]) + bia1;
        float b0 = lo32(acc1[o]) + bia0;
        float b1 = hi32(acc1[o]) + bia1;
        if (relu) {
            a0 = fmaxf(a0, 0.f); a1 = fmaxf(a1, 0.f);
            b0 = fmaxf(b0, 0.f); b1 = fmaxf(b1, 0.f);
        }
        size_t o0 = ((size_t)b * Cout + oc0 + 2*o)     * HWSZ;
        size_t o1 = ((size_t)b * Cout + oc0 + 2*o + 1) * HWSZ;
        out[o0 + gy0 * WW + gx] = a0;
        out[o1 + gy0 * WW + gx] = a1;
        out[o0 + gy1 * WW + gx] = b0;
        out[o1 + gy1 * WW + gx] = b1;
    }
}

// y: 0-7 f1(relu), 8-15 v1, 16-19 q, 20-23 k   (8 oc per block)
__global__ void __launch_bounds__(256, 4)
convA_kernel(const float* __restrict__ x,
             const float* __restrict__ w_f1, const float* __restrict__ b_f1,
             const float* __restrict__ w_v1, const float* __restrict__ b_v1,
             const float* __restrict__ w_q,  const float* __restrict__ b_q,
             const float* __restrict__ w_k,  const float* __restrict__ b_k) {
    int y = blockIdx.y, b = blockIdx.z;
    if (y < 8)       conv_body(x, nullptr, w_f1, b_f1, g_f1, y * 8,        1, b, CH);
    else if (y < 16) conv_body(x, nullptr, w_v1, b_v1, g_v1, (y - 8) * 8,  0, b, CH);
    else if (y < 20) conv_body(x, nullptr, w_q,  b_q,  g_q,  (y - 16) * 8, 0, b, QCH);
    else             conv_body(x, nullptr, w_k,  b_k,  g_k,  (y - 20) * 8, 0, b, QCH);
}

// y: 0-7 v2 on (v1+x), 8-15 f2 on f1 (relu)
__global__ void __launch_bounds__(256, 4)
convB_kernel(const float* __restrict__ x,
             const float* __restrict__ w_v2, const float* __restrict__ b_v2,
             const float* __restrict__ w_f2, const float* __restrict__ b_f2) {
    int y = blockIdx.y, b = blockIdx.z;
    if (y < 8) conv_body(g_v1, x,       w_v2, b_v2, g_v,  y * 8,       0, b, CH);
    else       conv_body(g_f1, nullptr, w_f2, b_f2, g_f2, (y - 8) * 8, 1, b, CH);
}

// ------------ fused: per-pixel sq sums -> masked 3x3 box -> inv norms ----------
__global__ void sqnorm_kernel() {
    __shared__ float sq[HWSZ], sk[HWSZ];
    const int b = blockIdx.x;
    const int tid = threadIdx.x;

    for (int p = tid; p < HWSZ; p += 1024) {
        float aq = 0.f, ak = 0.f;
#pragma unroll 4
        for (int c = 0; c < QCH; c++) {
            float qv = g_q[((size_t)b * QCH + c) * HWSZ + p];
            float kv = g_k[((size_t)b * QCH + c) * HWSZ + p];
            aq += qv * qv;
            ak += kv * kv;
        }
        sq[p] = aq;
        sk[p] = ak;
    }
    __syncthreads();

    for (int p = tid; p < HWSZ; p += 1024) {
        int y = p >> 6, x = p & 63;
        float aq = 0.f, ak = 0.f;
#pragma unroll
        for (int i = -1; i <= 1; i++) {
            int yy = y + i;
            if (yy < 0 || yy >= HH) continue;
#pragma unroll
            for (int j = -1; j <= 1; j++) {
                int xx = x + j;
                if (xx < 0 || xx >= WW) continue;
                aq += sq[yy * WW + xx];
                ak += sk[yy * WW + xx];
            }
        }
        g_invq[b * HWSZ + p] = 1.f / fmaxf(sqrtf(aq), 1e-12f);
        g_invk[b * HWSZ + p] = 1.f / fmaxf(sqrtf(ak), 1e-12f);
        g_pk[b * HWSZ + p] = 0ull;
    }
}

// ---------------- phase 1: D tile (K=32 GEMM, f32x2) + fused x-pass -> E -------
__global__ void __launch_bounds__(256, 2) gemmE_kernel() {
    extern __shared__ unsigned char smbuf[];
    u64*   As2  = (u64*)smbuf;                    // [32][128] dup (k,k)
    u64*   Qs2  = (u64*)(smbuf + 32768);          // [32][64] pairs (q_m, q_m+16)
    float* Qs2f = (float*)(smbuf + 32768);
    float* Ds   = (float*)smbuf;                  // [128][144] (after sync)

    const int b  = blockIdx.z;
    const int m0 = blockIdx.x * 128;
    const int l0 = blockIdx.y * 128;
    const int t  = threadIdx.x;

    const float* kb = g_k + (size_t)b * QCH * HWSZ;
    const float* qb = g_q + (size_t)b * QCH * HWSZ;

    {
        int c = t >> 3, sub = t & 7;
        const float* krow = kb + (size_t)c * HWSZ + l0 + sub * 16;
        const float* qrow = qb + (size_t)c * HWSZ + m0 + sub * 16;
#pragma unroll
        for (int g4 = 0; g4 < 4; g4++) {
            float4 kv = *(const float4*)(krow + g4 * 4);
            int L = sub * 16 + g4 * 4;
            As2[c * 128 + L + 0] = pack2(kv.x, kv.x);
            As2[c * 128 + L + 1] = pack2(kv.y, kv.y);
            As2[c * 128 + L + 2] = pack2(kv.z, kv.z);
            As2[c * 128 + L + 3] = pack2(kv.w, kv.w);
            float4 qv = *(const float4*)(qrow + g4 * 4);
            float qa[4] = {qv.x, qv.y, qv.z, qv.w};
#pragma unroll
            for (int e = 0; e < 4; e++) {
                int M = L + e;
                int a = M >> 5, r5 = M & 31;
                Qs2f[(c * 64 + a * 16 + (r5 & 15)) * 2 + (r5 >> 4)] = qa[e];
            }
        }
    }
    __syncthreads();

    const int tx = t & 15, ty = t >> 4;
    u64 acc2[8][4];
#pragma unroll
    for (int i = 0; i < 8; i++)
#pragma unroll
        for (int j = 0; j < 4; j++) acc2[i][j] = 0ull;

#pragma unroll 4
    for (int c = 0; c < QCH; c++) {
        u64 bb[4];
#pragma unroll
        for (int jp = 0; jp < 4; jp++) bb[jp] = Qs2[c * 64 + jp * 16 + tx];
        const ulonglong2* ap2 = (const ulonglong2*)&As2[c * 128 + ty * 8];
        ulonglong2 a01 = ap2[0];
        ulonglong2 a23 = ap2[1];
        ulonglong2 a45 = ap2[2];
        ulonglong2 a67 = ap2[3];
        u64 aa[8] = {a01.x, a01.y, a23.x, a23.y, a45.x, a45.y, a67.x, a67.y};
#pragma unroll
        for (int i = 0; i < 8; i++)
#pragma unroll
            for (int jp = 0; jp < 4; jp++)
                fma2(acc2[i][jp], aa[i], bb[jp]);
    }
    __syncthreads();

#pragma unroll
    for (int i = 0; i < 8; i++) {
        int row = ty * 8 + i;
#pragma unroll
        for (int jp = 0; jp < 4; jp++) {
            int col = jp * 32 + tx;
            Ds[row * 144 + col]      = lo32(acc2[i][jp]);
            Ds[row * 144 + col + 16] = hi32(acc2[i][jp]);
        }
    }
    __syncthreads();

    const int cg = t & 31, rg = t >> 5;
    const int c0 = cg * 4;
    float* Eout = g_E + ((size_t)b * HWSZ + l0) * HWSZ + m0;

#pragma unroll 2
    for (int it = 0; it < 16; it++) {
        int r  = it * 8 + rg;
        int lx = r & 63;
        bool rup = (lx >= 1), rdn = (lx <= 62);
        int rm = rup ? r - 1 : r;
        int rp = rdn ? r + 1 : r;
        const float* Rm = Ds + rm * 144;
        const float* R0 = Ds + r  * 144;
        const float* Rp = Ds + rp * 144;

        float4 mid = *(const float4*)(R0 + c0);
        float4 upA = (c0 > 0)   ? *(const float4*)(Rm + c0 - 4) : make_float4(0,0,0,0);
        float4 upB = *(const float4*)(Rm + c0);
        float4 dnA = *(const float4*)(Rp + c0);
        float4 dnB = (c0 < 124) ? *(const float4*)(Rp + c0 + 4) : make_float4(0,0,0,0);

        float4 res;
        res.x = mid.x + ((rup && (( c0      & 63) != 0 )) ? upA.w : 0.f)
                      + ((rdn && (( c0      & 63) != 63)) ? dnA.y : 0.f);
        res.y = mid.y + ((rup && (((c0 + 1) & 63) != 0 )) ? upB.x : 0.f)
                      + ((rdn && (((c0 + 1) & 63) != 63)) ? dnA.z : 0.f);
        res.z = mid.z + ((rup && (((c0 + 2) & 63) != 0 )) ? upB.y : 0.f)
                      + ((rdn && (((c0 + 2) & 63) != 63)) ? dnA.w : 0.f);
        res.w = mid.w + ((rup && (((c0 + 3) & 63) != 0 )) ? upB.z : 0.f)
                      + ((rdn && (((c0 + 3) & 63) != 63)) ? dnB.x : 0.f);

        *(float4*)(Eout + (size_t)r * HWSZ + c0) = res;
    }
}

// ---------------- phase 2: y-pass + normalize + argmax over l ------------------
__global__ void argmax_kernel() {
    const int b     = blockIdx.y;
    const int m0    = blockIdx.x * 128;
    const int lbase = blockIdx.z * 512;
    const int t     = threadIdx.x;
    const int mg    = t & 31;
    const int lane  = t >> 5;
    const int m     = m0 + mg * 4;

    const float4 invq4 = *(const float4*)(g_invq + b * HWSZ + m);
    const float* Eb = g_E + (size_t)b * HWSZ * HWSZ;
    const float* ik = g_invk + b * HWSZ;

    const bool mup = (m >= 64);
    const bool mdn = (m < HWSZ - 64);

    float bv0 = -2.f, bv1 = -2.f, bv2 = -2.f, bv3 = -2.f;
    int   bl0 = 0,    bl1 = 0,    bl2 = 0,    bl3 = 0;

#pragma unroll 4
    for (int l = lbase + lane; l < lbase + 512; l += 8) {
        const float* row = Eb + (size_t)l * HWSZ + m;
        float4 s = *(const float4*)row;
        float4 a = make_float4(0,0,0,0), c = make_float4(0,0,0,0);
        if (mup && l >= 64)
            a = *(const float4*)(row - 64 * HWSZ - 64);
        if (mdn && l < HWSZ - 64)
            c = *(const float4*)(row + 64 * HWSZ + 64);
        float ikl = ik[l];
        float r0 = (s.x + a.x + c.x) * ikl * invq4.x;
        float r1 = (s.y + a.y + c.y) * ikl * invq4.y;
        float r2 = (s.z + a.z + c.z) * ikl * invq4.z;
        float r3 = (s.w + a.w + c.w) * ikl * invq4.w;
        if (r0 > bv0) { bv0 = r0; bl0 = l; }
        if (r1 > bv1) { bv1 = r1; bl1 = l; }
        if (r2 > bv2) { bv2 = r2; bl2 = l; }
        if (r3 > bv3) { bv3 = r3; bl3 = l; }
    }

    __shared__ u64 sm[128];
    if (t < 128) sm[t] = 0ull;
    __syncthreads();

    atomicMax(&sm[mg * 4 + 0], ((u64)fkey(bv0) << 32) | (unsigned)(~bl0));
    atomicMax(&sm[mg * 4 + 1], ((u64)fkey(bv1) << 32) | (unsigned)(~bl1));
    atomicMax(&sm[mg * 4 + 2], ((u64)fkey(bv2) << 32) | (unsigned)(~bl2));
    atomicMax(&sm[mg * 4 + 3], ((u64)fkey(bv3) << 32) | (unsigned)(~bl3));
    __syncthreads();

    if (t < 128)
        atomicMax(&g_pk[b * HWSZ + m0 + t], sm[t]);
}

// ---------------- gather selected patches, fold, combine -----------------------
__global__ void final_kernel(const float* __restrict__ x, float* __restrict__ out) {
    const int idx = blockIdx.x * 256 + threadIdx.x;
    const int xx = idx & 63;
    const int yy = (idx >> 6) & 63;
    const int c  = (idx >> 12) & 63;
    const int b  = idx >> 18;

    const float* vb = g_v + ((size_t)b * CH + c) * HWSZ;
    const u64* pb = g_pk + (size_t)b * HWSZ;

    float T = 0.f;
#pragma unroll
    for (int i = 0; i < 3; i++) {
#pragma unroll
        for (int j = 0; j < 3; j++) {
            int ny = yy + 1 - i, nx = xx + 1 - j;
            if (ny >= 0 && ny < HH && nx >= 0 && nx < WW) {
                u64 p = pb[ny * WW + nx];
                int l = (int)(~(unsigned)p);
                int ry = l >> 6, rx = l & 63;
                int vy = ry + i - 1, vx = rx + j - 1;
                if (vy >= 0 && vy < HH && vx >= 0 && vx < WW)
                    T += vb[vy * WW + vx];
            }
        }
    }

    u64 pc = pb[yy * WW + xx];
    unsigned key = (unsigned)(pc >> 32);
    unsigned bits = (key & 0x80000000u) ? (key ^ 0x80000000u) : ~key;
    float S = __uint_as_float(bits);

    out[idx] = g_f2[idx] + x[idx] + (T * (1.f / 9.f)) * S;
}

// -------------------------------------------------------------------------------
extern "C" void kernel_launch(void* const* d_in, const int* in_sizes, int n_in,
                              void* d_out, int out_size) {
    const float* x    = (const float*)d_in[0];
    const float* w_f1 = (const float*)d_in[1];
    const float* b_f1 = (const float*)d_in[2];
    const float* w_f2 = (const float*)d_in[3];
    const float* b_f2 = (const float*)d_in[4];
    const float* w_v1 = (const float*)d_in[5];
    const float* b_v1 = (const float*)d_in[6];
    const float* w_v2 = (const float*)d_in[7];
    const float* b_v2 = (const float*)d_in[8];
    const float* w_q  = (const float*)d_in[9];
    const float* b_q  = (const float*)d_in[10];
    const float* w_k  = (const float*)d_in[11];
    const float* b_k  = (const float*)d_in[12];
    float* out = (float*)d_out;

    cudaFuncSetAttribute(gemmE_kernel,
                         cudaFuncAttributeMaxDynamicSharedMemorySize, 73728);

    dim3 blk(256);

    // slot 1: all convs reading x (produces q,k needed by gemmE)
    convA_kernel<<<dim3(8, 24, BATCH), blk>>>(x, w_f1, b_f1, w_v1, b_v1,
                                              w_q, b_q, w_k, b_k);
    // slot 2: GEMM + x-pass (fp32 E)
    gemmE_kernel<<<dim3(32, 32, BATCH), blk, 73728>>>();
    // slot 3: norms + g_pk init
    sqnorm_kernel<<<dim3(BATCH), dim3(1024)>>>();
    // slot 4: dependent convs (profiled slot — verify occ 4, regs <= 64)
    convB_kernel<<<dim3(8, 16, BATCH), blk>>>(x, w_v2, b_v2, w_f2, b_f2);
    // slot 5: argmax
    argmax_kernel<<<dim3(32, BATCH, 8), blk>>>();
    // slot 6: gather/fold/combine
    final_kernel<<<dim3(4096), blk>>>(x, out);
}

// round 12
// speedup vs baseline: 1.1202x; 1.1202x over previous
#include <cuda_runtime.h>

#define HH 64
#define WW 64
#define HWSZ 4096          // 64*64
#define CH 64
#define QCH 32
#define BATCH 4

typedef unsigned long long u64;

// ---------------- scratch (device globals; no allocation allowed) -------------
__device__ float g_v1[BATCH*CH*HWSZ];
__device__ float g_v [BATCH*CH*HWSZ];
__device__ float g_f1[BATCH*CH*HWSZ];
__device__ float g_f2[BATCH*CH*HWSZ];
__device__ float g_q [BATCH*QCH*HWSZ];
__device__ float g_k [BATCH*QCH*HWSZ];
__device__ float g_invq[BATCH*HWSZ];
__device__ float g_invk[BATCH*HWSZ];
__device__ u64   g_pk[BATCH*HWSZ];                 // packed (fkey(max)<<32)|~argmax
__device__ float g_E[(size_t)BATCH*HWSZ*HWSZ];     // x-pass box-summed dots (fp32)

// ---------------- helpers -----------------------------------------------------
__device__ __forceinline__ unsigned fkey(float f) {
    unsigned u = __float_as_uint(f);
    return (u & 0x80000000u) ? ~u : (u | 0x80000000u);
}
__device__ __forceinline__ u64 pack2(float lo, float hi) {
    u64 r;
    asm("mov.b64 %0, {%1, %2};" : "=l"(r)
        : "r"(__float_as_uint(lo)), "r"(__float_as_uint(hi)));
    return r;
}
__device__ __forceinline__ void fma2(u64 &d, u64 a, u64 b) {
    asm("fma.rn.f32x2 %0, %1, %2, %0;" : "+l"(d) : "l"(a), "l"(b));
}
__device__ __forceinline__ float lo32(u64 v) { return __uint_as_float((unsigned)v); }
__device__ __forceinline__ float hi32(u64 v) { return __uint_as_float((unsigned)(v >> 32)); }
__device__ __forceinline__ u64 u64max_(u64 a, u64 b) { return a > b ? a : b; }

// ---------------- 3x3 same conv body, Cin=64, NCHW, f32x2 ---------------------
// block: 256 threads; spatial tile 32(h) x 16(w); each thread: 2 pixels x 16 oc.
__device__ __forceinline__ void conv_body(const float* __restrict__ in,
                                          const float* __restrict__ in2,
                                          const float* __restrict__ w,
                                          const float* __restrict__ bias,
                                          float* __restrict__ out,
                                          int oc0, int relu, int b, int Cout) {
    __shared__ float tile[16][34][18];   // [ci][y][x] halo tile
    __shared__ u64 ws2[16*9*8];          // [ci][tap][ocpair]

    const int tid = threadIdx.x;
    const int px = tid & 15, py = tid >> 4;
    const int ty0 = (blockIdx.x >> 2) * 32;
    const int tx0 = (blockIdx.x & 3) * 16;

    u64 acc0[8], acc1[8];
#pragma unroll
    for (int o = 0; o < 8; o++) { acc0[o] = 0ull; acc1[o] = 0ull; }

    const float* inb  = in  + (size_t)b * CH * HWSZ;
    const float* in2b = in2 ? in2 + (size_t)b * CH * HWSZ : nullptr;

    for (int c0 = 0; c0 < CH; c0 += 16) {
        for (int idx = tid; idx < 16*34*18; idx += 256) {
            int ci  = idx / 612;
            int rem = idx - ci * 612;
            int yy  = rem / 18, xx = rem - yy * 18;
            int gy = ty0 + yy - 1, gx = tx0 + xx - 1;
            float val = 0.f;
            if (gy >= 0 && gy < HH && gx >= 0 && gx < WW) {
                size_t off = (size_t)(c0 + ci) * HWSZ + gy * WW + gx;
                val = inb[off];
                if (in2b) val += in2b[off];
            }
            tile[ci][yy][xx] = val;
        }
        for (int idx = tid; idx < 16*9*8; idx += 256) {
            int o  = idx & 7;
            int tt = (idx >> 3) % 9;
            int ci = idx / 72;
            float w0 = w[((size_t)(oc0 + 2*o)     * CH + (c0 + ci)) * 9 + tt];
            float w1 = w[((size_t)(oc0 + 2*o + 1) * CH + (c0 + ci)) * 9 + tt];
            ws2[idx] = pack2(w0, w1);
        }
        __syncthreads();

#pragma unroll 2
        for (int ci = 0; ci < 16; ci++) {
#pragma unroll
            for (int t = 0; t < 9; t++) {
                const int dy = t / 3, dx = t - 3 * (t / 3);
                float xv0 = tile[ci][py + dy][px + dx];
                float xv1 = tile[ci][py + 16 + dy][px + dx];
                u64 x02 = pack2(xv0, xv0);
                u64 x12 = pack2(xv1, xv1);
                const u64* wp = &ws2[(ci * 9 + t) * 8];
#pragma unroll
                for (int o = 0; o < 8; o++) {
                    u64 wv = wp[o];
                    fma2(acc0[o], x02, wv);
                    fma2(acc1[o], x12, wv);
                }
            }
        }
        __syncthreads();
    }

    const int gx = tx0 + px;
    const int gy0 = ty0 + py, gy1 = ty0 + py + 16;
#pragma unroll
    for (int o = 0; o < 8; o++) {
        float bia0 = bias[oc0 + 2*o], bia1 = bias[oc0 + 2*o + 1];
        float a0 = lo32(acc0[o]) + bia0;
        float a1 = hi32(acc0[o]) + bia1;
        float b0 = lo32(acc1[o]) + bia0;
        float b1 = hi32(acc1[o]) + bia1;
        if (relu) {
            a0 = fmaxf(a0, 0.f); a1 = fmaxf(a1, 0.f);
            b0 = fmaxf(b0, 0.f); b1 = fmaxf(b1, 0.f);
        }
        size_t o0 = ((size_t)b * Cout + oc0 + 2*o)     * HWSZ;
        size_t o1 = ((size_t)b * Cout + oc0 + 2*o + 1) * HWSZ;
        out[o0 + gy0 * WW + gx] = a0;
        out[o1 + gy0 * WW + gx] = a1;
        out[o0 + gy1 * WW + gx] = b0;
        out[o1 + gy1 * WW + gx] = b1;
    }
}

__global__ void __launch_bounds__(256, 3)
convA_kernel(const float* __restrict__ x,
             const float* __restrict__ w_f1, const float* __restrict__ b_f1,
             const float* __restrict__ w_v1, const float* __restrict__ b_v1,
             const float* __restrict__ w_q,  const float* __restrict__ b_q,
             const float* __restrict__ w_k,  const float* __restrict__ b_k) {
    int y = blockIdx.y, b = blockIdx.z;
    if (y < 4)       conv_body(x, nullptr, w_f1, b_f1, g_f1, y * 16,        1, b, CH);
    else if (y < 8)  conv_body(x, nullptr, w_v1, b_v1, g_v1, (y - 4) * 16,  0, b, CH);
    else if (y < 10) conv_body(x, nullptr, w_q,  b_q,  g_q,  (y - 8) * 16,  0, b, QCH);
    else             conv_body(x, nullptr, w_k,  b_k,  g_k,  (y - 10) * 16, 0, b, QCH);
}

__global__ void __launch_bounds__(256, 3)
convB_kernel(const float* __restrict__ x,
             const float* __restrict__ w_v2, const float* __restrict__ b_v2,
             const float* __restrict__ w_f2, const float* __restrict__ b_f2) {
    int y = blockIdx.y, b = blockIdx.z;
    if (y < 4) conv_body(g_v1, x,       w_v2, b_v2, g_v,  y * 16,       0, b, CH);
    else       conv_body(g_f1, nullptr, w_f2, b_f2, g_f2, (y - 4) * 16, 1, b, CH);
}

// ------------ fused: per-pixel sq sums -> masked 3x3 box -> inv norms ----------
__global__ void sqnorm_kernel() {
    __shared__ float sq[HWSZ], sk[HWSZ];
    const int b = blockIdx.x;
    const int tid = threadIdx.x;

    for (int p = tid; p < HWSZ; p += 1024) {
        float aq = 0.f, ak = 0.f;
#pragma unroll 4
        for (int c = 0; c < QCH; c++) {
            float qv = g_q[((size_t)b * QCH + c) * HWSZ + p];
            float kv = g_k[((size_t)b * QCH + c) * HWSZ + p];
            aq += qv * qv;
            ak += kv * kv;
        }
        sq[p] = aq;
        sk[p] = ak;
    }
    __syncthreads();

    for (int p = tid; p < HWSZ; p += 1024) {
        int y = p >> 6, x = p & 63;
        float aq = 0.f, ak = 0.f;
#pragma unroll
        for (int i = -1; i <= 1; i++) {
            int yy = y + i;
            if (yy < 0 || yy >= HH) continue;
#pragma unroll
            for (int j = -1; j <= 1; j++) {
                int xx = x + j;
                if (xx < 0 || xx >= WW) continue;
                aq += sq[yy * WW + xx];
                ak += sk[yy * WW + xx];
            }
        }
        g_invq[b * HWSZ + p] = 1.f / fmaxf(sqrtf(aq), 1e-12f);
        g_invk[b * HWSZ + p] = 1.f / fmaxf(sqrtf(ak), 1e-12f);
        g_pk[b * HWSZ + p] = 0ull;
    }
}

// ---------------- phase 1: D tile (K=32 GEMM, f32x2) + fused x-pass -> E -------
__global__ void __launch_bounds__(256, 2) gemmE_kernel() {
    extern __shared__ unsigned char smbuf[];
    u64*   As2  = (u64*)smbuf;                    // [32][128] dup (k,k)
    u64*   Qs2  = (u64*)(smbuf + 32768);          // [32][64] pairs (q_m, q_m+16)
    float* Qs2f = (float*)(smbuf + 32768);
    float* Ds   = (float*)smbuf;                  // [128][144] (after sync)

    const int b  = blockIdx.z;
    const int m0 = blockIdx.x * 128;
    const int l0 = blockIdx.y * 128;
    const int t  = threadIdx.x;

    const float* kb = g_k + (size_t)b * QCH * HWSZ;
    const float* qb = g_q + (size_t)b * QCH * HWSZ;

    {
        int c = t >> 3, sub = t & 7;
        const float* krow = kb + (size_t)c * HWSZ + l0 + sub * 16;
        const float* qrow = qb + (size_t)c * HWSZ + m0 + sub * 16;
#pragma unroll
        for (int g4 = 0; g4 < 4; g4++) {
            float4 kv = *(const float4*)(krow + g4 * 4);
            int L = sub * 16 + g4 * 4;
            As2[c * 128 + L + 0] = pack2(kv.x, kv.x);
            As2[c * 128 + L + 1] = pack2(kv.y, kv.y);
            As2[c * 128 + L + 2] = pack2(kv.z, kv.z);
            As2[c * 128 + L + 3] = pack2(kv.w, kv.w);
            float4 qv = *(const float4*)(qrow + g4 * 4);
            float qa[4] = {qv.x, qv.y, qv.z, qv.w};
#pragma unroll
            for (int e = 0; e < 4; e++) {
                int M = L + e;
                int a = M >> 5, r5 = M & 31;
                Qs2f[(c * 64 + a * 16 + (r5 & 15)) * 2 + (r5 >> 4)] = qa[e];
            }
        }
    }
    __syncthreads();

    const int tx = t & 15, ty = t >> 4;
    u64 acc2[8][4];
#pragma unroll
    for (int i = 0; i < 8; i++)
#pragma unroll
        for (int j = 0; j < 4; j++) acc2[i][j] = 0ull;

#pragma unroll 4
    for (int c = 0; c < QCH; c++) {
        u64 bb[4];
#pragma unroll
        for (int jp = 0; jp < 4; jp++) bb[jp] = Qs2[c * 64 + jp * 16 + tx];
        const ulonglong2* ap2 = (const ulonglong2*)&As2[c * 128 + ty * 8];
        ulonglong2 a01 = ap2[0];
        ulonglong2 a23 = ap2[1];
        ulonglong2 a45 = ap2[2];
        ulonglong2 a67 = ap2[3];
        u64 aa[8] = {a01.x, a01.y, a23.x, a23.y, a45.x, a45.y, a67.x, a67.y};
#pragma unroll
        for (int i = 0; i < 8; i++)
#pragma unroll
            for (int jp = 0; jp < 4; jp++)
                fma2(acc2[i][jp], aa[i], bb[jp]);
    }
    __syncthreads();

#pragma unroll
    for (int i = 0; i < 8; i++) {
        int row = ty * 8 + i;
#pragma unroll
        for (int jp = 0; jp < 4; jp++) {
            int col = jp * 32 + tx;
            Ds[row * 144 + col]      = lo32(acc2[i][jp]);
            Ds[row * 144 + col + 16] = hi32(acc2[i][jp]);
        }
    }
    __syncthreads();

    const int cg = t & 31, rg = t >> 5;
    const int c0 = cg * 4;
    float* Eout = g_E + ((size_t)b * HWSZ + l0) * HWSZ + m0;

#pragma unroll 2
    for (int it = 0; it < 16; it++) {
        int r  = it * 8 + rg;
        int lx = r & 63;
        bool rup = (lx >= 1), rdn = (lx <= 62);
        int rm = rup ? r - 1 : r;
        int rp = rdn ? r + 1 : r;
        const float* Rm = Ds + rm * 144;
        const float* R0 = Ds + r  * 144;
        const float* Rp = Ds + rp * 144;

        float4 mid = *(const float4*)(R0 + c0);
        float4 upA = (c0 > 0)   ? *(const float4*)(Rm + c0 - 4) : make_float4(0,0,0,0);
        float4 upB = *(const float4*)(Rm + c0);
        float4 dnA = *(const float4*)(Rp + c0);
        float4 dnB = (c0 < 124) ? *(const float4*)(Rp + c0 + 4) : make_float4(0,0,0,0);

        float4 res;
        res.x = mid.x + ((rup && (( c0      & 63) != 0 )) ? upA.w : 0.f)
                      + ((rdn && (( c0      & 63) != 63)) ? dnA.y : 0.f);
        res.y = mid.y + ((rup && (((c0 + 1) & 63) != 0 )) ? upB.x : 0.f)
                      + ((rdn && (((c0 + 1) & 63) != 63)) ? dnA.z : 0.f);
        res.z = mid.z + ((rup && (((c0 + 2) & 63) != 0 )) ? upB.y : 0.f)
                      + ((rdn && (((c0 + 2) & 63) != 63)) ? dnA.w : 0.f);
        res.w = mid.w + ((rup && (((c0 + 3) & 63) != 0 )) ? upB.z : 0.f)
                      + ((rdn && (((c0 + 3) & 63) != 63)) ? dnB.x : 0.f);

        *(float4*)(Eout + (size_t)r * HWSZ + c0) = res;
    }
}

// ---------------- phase 2: y-pass + normalize + argmax over l ------------------
__global__ void argmax_kernel() {
    const int b     = blockIdx.y;
    const int m0    = blockIdx.x * 128;
    const int lbase = blockIdx.z * 512;
    const int t     = threadIdx.x;
    const int mg    = t & 31;
    const int lane  = t >> 5;
    const int m     = m0 + mg * 4;

    const float4 invq4 = *(const float4*)(g_invq + b * HWSZ + m);
    const float* Eb = g_E + (size_t)b * HWSZ * HWSZ;
    const float* ik = g_invk + b * HWSZ;

    const bool mup = (m >= 64);
    const bool mdn = (m < HWSZ - 64);

    float bv0 = -2.f, bv1 = -2.f, bv2 = -2.f, bv3 = -2.f;
    int   bl0 = 0,    bl1 = 0,    bl2 = 0,    bl3 = 0;

#pragma unroll 4
    for (int l = lbase + lane; l < lbase + 512; l += 8) {
        const float* row = Eb + (size_t)l * HWSZ + m;
        float4 s = *(const float4*)row;
        float4 a = make_float4(0,0,0,0), c = make_float4(0,0,0,0);
        if (mup && l >= 64)
            a = *(const float4*)(row - 64 * HWSZ - 64);
        if (mdn && l < HWSZ - 64)
            c = *(const float4*)(row + 64 * HWSZ + 64);
        float ikl = ik[l];
        float r0 = (s.x + a.x + c.x) * ikl * invq4.x;
        float r1 = (s.y + a.y + c.y) * ikl * invq4.y;
        float r2 = (s.z + a.z + c.z) * ikl * invq4.z;
        float r3 = (s.w + a.w + c.w) * ikl * invq4.w;
        if (r0 > bv0) { bv0 = r0; bl0 = l; }
        if (r1 > bv1) { bv1 = r1; bl1 = l; }
        if (r2 > bv2) { bv2 = r2; bl2 = l; }
        if (r3 > bv3) { bv3 = r3; bl3 = l; }
    }

    __shared__ u64 sm[128];
    if (t < 128) sm[t] = 0ull;
    __syncthreads();

    atomicMax(&sm[mg * 4 + 0], ((u64)fkey(bv0) << 32) | (unsigned)(~bl0));
    atomicMax(&sm[mg * 4 + 1], ((u64)fkey(bv1) << 32) | (unsigned)(~bl1));
    atomicMax(&sm[mg * 4 + 2], ((u64)fkey(bv2) << 32) | (unsigned)(~bl2));
    atomicMax(&sm[mg * 4 + 3], ((u64)fkey(bv3) << 32) | (unsigned)(~bl3));
    __syncthreads();

    if (t < 128)
        atomicMax(&g_pk[b * HWSZ + m0 + t], sm[t]);
}

// ---------------- gather selected patches, fold, combine -----------------------
__global__ void final_kernel(const float* __restrict__ x, float* __restrict__ out) {
    const int idx = blockIdx.x * 256 + threadIdx.x;
    const int xx = idx & 63;
    const int yy = (idx >> 6) & 63;
    const int c  = (idx >> 12) & 63;
    const int b  = idx >> 18;

    const float* vb = g_v + ((size_t)b * CH + c) * HWSZ;
    const u64* pb = g_pk + (size_t)b * HWSZ;

    float T = 0.f;
#pragma unroll
    for (int i = 0; i < 3; i++) {
#pragma unroll
        for (int j = 0; j < 3; j++) {
            int ny = yy + 1 - i, nx = xx + 1 - j;
            if (ny >= 0 && ny < HH && nx >= 0 && nx < WW) {
                u64 p = pb[ny * WW + nx];
                int l = (int)(~(unsigned)p);
                int ry = l >> 6, rx = l & 63;
                int vy = ry + i - 1, vx = rx + j - 1;
                if (vy >= 0 && vy < HH && vx >= 0 && vx < WW)
                    T += vb[vy * WW + vx];
            }
        }
    }

    u64 pc = pb[yy * WW + xx];
    unsigned key = (unsigned)(pc >> 32);
    unsigned bits = (key & 0x80000000u) ? (key ^ 0x80000000u) : ~key;
    float S = __uint_as_float(bits);

    out[idx] = g_f2[idx] + x[idx] + (T * (1.f / 9.f)) * S;
}

// -------------------------------------------------------------------------------
extern "C" void kernel_launch(void* const* d_in, const int* in_sizes, int n_in,
                              void* d_out, int out_size) {
    const float* x    = (const float*)d_in[0];
    const float* w_f1 = (const float*)d_in[1];
    const float* b_f1 = (const float*)d_in[2];
    const float* w_f2 = (const float*)d_in[3];
    const float* b_f2 = (const float*)d_in[4];
    const float* w_v1 = (const float*)d_in[5];
    const float* b_v1 = (const float*)d_in[6];
    const float* w_v2 = (const float*)d_in[7];
    const float* b_v2 = (const float*)d_in[8];
    const float* w_q  = (const float*)d_in[9];
    const float* b_q  = (const float*)d_in[10];
    const float* w_k  = (const float*)d_in[11];
    const float* b_k  = (const float*)d_in[12];
    float* out = (float*)d_out;

    static cudaStream_t s1 = nullptr;
    static cudaEvent_t evA = nullptr, evB = nullptr;
    if (!s1) {
        cudaStreamCreateWithFlags(&s1, cudaStreamNonBlocking);
        cudaEventCreateWithFlags(&evA, cudaEventDisableTiming);
        cudaEventCreateWithFlags(&evB, cudaEventDisableTiming);
    }

    cudaFuncSetAttribute(gemmE_kernel,
                         cudaFuncAttributeMaxDynamicSharedMemorySize, 73728);

    dim3 blk(256);

    // main stream: convA -> gemmE -> sqnorm -> argmax -> (join) -> final
    convA_kernel<<<dim3(8, 12, BATCH), blk>>>(x, w_f1, b_f1, w_v1, b_v1,
                                              w_q, b_q, w_k, b_k);
    cudaEventRecord(evA, 0);

    // side stream: convB (needs only convA outputs + x), overlaps with gemmE/argmax
    cudaStreamWaitEvent(s1, evA, 0);
    convB_kernel<<<dim3(8, 8, BATCH), blk, 0, s1>>>(x, w_v2, b_v2, w_f2, b_f2);
    cudaEventRecord(evB, s1);

    gemmE_kernel<<<dim3(32, 32, BATCH), blk, 73728>>>();
    sqnorm_kernel<<<dim3(BATCH), dim3(1024)>>>();
    argmax_kernel<<<dim3(32, BATCH, 8), blk>>>();

    // join convB before final (final reads g_v, g_f2)
    cudaStreamWaitEvent(0, evB, 0);
    final_kernel<<<dim3(4096), blk>>>(x, out);
}

// round 13
// speedup vs baseline: 1.2629x; 1.1274x over previous
#include <cuda_runtime.h>

#define HH 64
#define WW 64
#define HWSZ 4096          // 64*64
#define CH 64
#define QCH 32
#define BATCH 4

typedef unsigned long long u64;

// ---------------- scratch (device globals; no allocation allowed) -------------
__device__ float g_v1[BATCH*CH*HWSZ];
__device__ float g_v [BATCH*CH*HWSZ];
__device__ float g_f1[BATCH*CH*HWSZ];
__device__ float g_f2[BATCH*CH*HWSZ];
__device__ float g_q [BATCH*QCH*HWSZ];
__device__ float g_k [BATCH*QCH*HWSZ];
__device__ float g_sqq[BATCH*HWSZ];
__device__ float g_sqk[BATCH*HWSZ];
__device__ float g_invq[BATCH*HWSZ];
__device__ float g_invk[BATCH*HWSZ];
__device__ u64   g_pk[BATCH*HWSZ];                 // packed (fkey(max)<<32)|~argmax
__device__ float g_E[(size_t)BATCH*HWSZ*HWSZ];     // x-pass box-summed dots (fp32)

// ---------------- helpers -----------------------------------------------------
__device__ __forceinline__ unsigned fkey(float f) {
    unsigned u = __float_as_uint(f);
    return (u & 0x80000000u) ? ~u : (u | 0x80000000u);
}
__device__ __forceinline__ u64 pack2(float lo, float hi) {
    u64 r;
    asm("mov.b64 %0, {%1, %2};" : "=l"(r)
        : "r"(__float_as_uint(lo)), "r"(__float_as_uint(hi)));
    return r;
}
__device__ __forceinline__ void fma2(u64 &d, u64 a, u64 b) {
    asm("fma.rn.f32x2 %0, %1, %2, %0;" : "+l"(d) : "l"(a), "l"(b));
}
__device__ __forceinline__ float lo32(u64 v) { return __uint_as_float((unsigned)v); }
__device__ __forceinline__ float hi32(u64 v) { return __uint_as_float((unsigned)(v >> 32)); }
__device__ __forceinline__ u64 u64max_(u64 a, u64 b) { return a > b ? a : b; }

// ---------------- 3x3 same conv body, Cin=64, NCHW, f32x2 ---------------------
// block: 256 threads; spatial tile 32(h) x 16(w); each thread: 2 pixels x 16 oc.
__device__ __forceinline__ void conv_body(const float* __restrict__ in,
                                          const float* __restrict__ in2,
                                          const float* __restrict__ w,
                                          const float* __restrict__ bias,
                                          float* __restrict__ out,
                                          int oc0, int relu, int b, int Cout) {
    __shared__ float tile[16][34][18];   // [ci][y][x] halo tile
    __shared__ u64 ws2[16*9*8];          // [ci][tap][ocpair]

    const int tid = threadIdx.x;
    const int px = tid & 15, py = tid >> 4;
    const int ty0 = (blockIdx.x >> 2) * 32;
    const int tx0 = (blockIdx.x & 3) * 16;

    u64 acc0[8], acc1[8];
#pragma unroll
    for (int o = 0; o < 8; o++) { acc0[o] = 0ull; acc1[o] = 0ull; }

    const float* inb  = in  + (size_t)b * CH * HWSZ;
    const float* in2b = in2 ? in2 + (size_t)b * CH * HWSZ : nullptr;

    for (int c0 = 0; c0 < CH; c0 += 16) {
        for (int idx = tid; idx < 16*34*18; idx += 256) {
            int ci  = idx / 612;
            int rem = idx - ci * 612;
            int yy  = rem / 18, xx = rem - yy * 18;
            int gy = ty0 + yy - 1, gx = tx0 + xx - 1;
            float val = 0.f;
            if (gy >= 0 && gy < HH && gx >= 0 && gx < WW) {
                size_t off = (size_t)(c0 + ci) * HWSZ + gy * WW + gx;
                val = inb[off];
                if (in2b) val += in2b[off];
            }
            tile[ci][yy][xx] = val;
        }
        for (int idx = tid; idx < 16*9*8; idx += 256) {
            int o  = idx & 7;
            int tt = (idx >> 3) % 9;
            int ci = idx / 72;
            float w0 = w[((size_t)(oc0 + 2*o)     * CH + (c0 + ci)) * 9 + tt];
            float w1 = w[((size_t)(oc0 + 2*o + 1) * CH + (c0 + ci)) * 9 + tt];
            ws2[idx] = pack2(w0, w1);
        }
        __syncthreads();

#pragma unroll 2
        for (int ci = 0; ci < 16; ci++) {
#pragma unroll
            for (int t = 0; t < 9; t++) {
                const int dy = t / 3, dx = t - 3 * (t / 3);
                float xv0 = tile[ci][py + dy][px + dx];
                float xv1 = tile[ci][py + 16 + dy][px + dx];
                u64 x02 = pack2(xv0, xv0);
                u64 x12 = pack2(xv1, xv1);
                const u64* wp = &ws2[(ci * 9 + t) * 8];
#pragma unroll
                for (int o = 0; o < 8; o++) {
                    u64 wv = wp[o];
                    fma2(acc0[o], x02, wv);
                    fma2(acc1[o], x12, wv);
                }
            }
        }
        __syncthreads();
    }

    const int gx = tx0 + px;
    const int gy0 = ty0 + py, gy1 = ty0 + py + 16;
#pragma unroll
    for (int o = 0; o < 8; o++) {
        float bia0 = bias[oc0 + 2*o], bia1 = bias[oc0 + 2*o + 1];
        float a0 = lo32(acc0[o]) + bia0;
        float a1 = hi32(acc0[o]) + bia1;
        float b0 = lo32(acc1[o]) + bia0;
        float b1 = hi32(acc1[o]) + bia1;
        if (relu) {
            a0 = fmaxf(a0, 0.f); a1 = fmaxf(a1, 0.f);
            b0 = fmaxf(b0, 0.f); b1 = fmaxf(b1, 0.f);
        }
        size_t o0 = ((size_t)b * Cout + oc0 + 2*o)     * HWSZ;
        size_t o1 = ((size_t)b * Cout + oc0 + 2*o + 1) * HWSZ;
        out[o0 + gy0 * WW + gx] = a0;
        out[o1 + gy0 * WW + gx] = a1;
        out[o0 + gy1 * WW + gx] = b0;
        out[o1 + gy1 * WW + gx] = b1;
    }
}

__global__ void __launch_bounds__(256, 3)
convA_kernel(const float* __restrict__ x,
             const float* __restrict__ w_f1, const float* __restrict__ b_f1,
             const float* __restrict__ w_v1, const float* __restrict__ b_v1,
             const float* __restrict__ w_q,  const float* __restrict__ b_q,
             const float* __restrict__ w_k,  const float* __restrict__ b_k) {
    int y = blockIdx.y, b = blockIdx.z;
    if (y < 4)       conv_body(x, nullptr, w_f1, b_f1, g_f1, y * 16,        1, b, CH);
    else if (y < 8)  conv_body(x, nullptr, w_v1, b_v1, g_v1, (y - 4) * 16,  0, b, CH);
    else if (y < 10) conv_body(x, nullptr, w_q,  b_q,  g_q,  (y - 8) * 16,  0, b, QCH);
    else             conv_body(x, nullptr, w_k,  b_k,  g_k,  (y - 10) * 16, 0, b, QCH);
}

__global__ void __launch_bounds__(256, 3)
convB_kernel(const float* __restrict__ x,
             const float* __restrict__ w_v2, const float* __restrict__ b_v2,
             const float* __restrict__ w_f2, const float* __restrict__ b_f2) {
    int y = blockIdx.y, b = blockIdx.z;
    if (y < 4) conv_body(g_v1, x,       w_v2, b_v2, g_v,  y * 16,       0, b, CH);
    else       conv_body(g_f1, nullptr, w_f2, b_f2, g_f2, (y - 4) * 16, 1, b, CH);
}

// ---------------- per-pixel squared channel sums (grid 16 x B) -----------------
__global__ void sqsum_kernel() {
    int b = blockIdx.y;
    int p = blockIdx.x * 256 + threadIdx.x;
    float sq = 0.f, sk = 0.f;
#pragma unroll 4
    for (int c = 0; c < QCH; c++) {
        float qv = g_q[((size_t)b * QCH + c) * HWSZ + p];
        float kv = g_k[((size_t)b * QCH + c) * HWSZ + p];
        sq += qv * qv;
        sk += kv * kv;
    }
    g_sqq[b * HWSZ + p] = sq;
    g_sqk[b * HWSZ + p] = sk;
}

// masked 3x3 box-sum -> inverse patch norms; also zero g_pk (grid 16 x B)
__global__ void norm_kernel() {
    int b = blockIdx.y;
    int p = blockIdx.x * 256 + threadIdx.x;
    int y = p >> 6, x = p & 63;
    float sq = 0.f, sk = 0.f;
#pragma unroll
    for (int i = -1; i <= 1; i++) {
        int yy = y + i;
        if (yy < 0 || yy >= HH) continue;
#pragma unroll
        for (int j = -1; j <= 1; j++) {
            int xx = x + j;
            if (xx < 0 || xx >= WW) continue;
            int q = b * HWSZ + yy * WW + xx;
            sq += g_sqq[q];
            sk += g_sqk[q];
        }
    }
    g_invq[b * HWSZ + p] = 1.f / fmaxf(sqrtf(sq), 1e-12f);
    g_invk[b * HWSZ + p] = 1.f / fmaxf(sqrtf(sk), 1e-12f);
    g_pk[b * HWSZ + p] = 0ull;
}

// ---------------- phase 1: D tile (K=32 GEMM, f32x2) + fused x-pass -> E -------
__global__ void __launch_bounds__(256, 2) gemmE_kernel() {
    extern __shared__ unsigned char smbuf[];
    u64*   As2  = (u64*)smbuf;                    // [32][128] dup (k,k)
    u64*   Qs2  = (u64*)(smbuf + 32768);          // [32][64] pairs (q_m, q_m+16)
    float* Qs2f = (float*)(smbuf + 32768);
    float* Ds   = (float*)smbuf;                  // [128][144] (after sync)

    const int b  = blockIdx.z;
    const int m0 = blockIdx.x * 128;
    const int l0 = blockIdx.y * 128;
    const int t  = threadIdx.x;

    const float* kb = g_k + (size_t)b * QCH * HWSZ;
    const float* qb = g_q + (size_t)b * QCH * HWSZ;

    {
        int c = t >> 3, sub = t & 7;
        const float* krow = kb + (size_t)c * HWSZ + l0 + sub * 16;
        const float* qrow = qb + (size_t)c * HWSZ + m0 + sub * 16;
#pragma unroll
        for (int g4 = 0; g4 < 4; g4++) {
            float4 kv = *(const float4*)(krow + g4 * 4);
            int L = sub * 16 + g4 * 4;
            As2[c * 128 + L + 0] = pack2(kv.x, kv.x);
            As2[c * 128 + L + 1] = pack2(kv.y, kv.y);
            As2[c * 128 + L + 2] = pack2(kv.z, kv.z);
            As2[c * 128 + L + 3] = pack2(kv.w, kv.w);
            float4 qv = *(const float4*)(qrow + g4 * 4);
            float qa[4] = {qv.x, qv.y, qv.z, qv.w};
#pragma unroll
            for (int e = 0; e < 4; e++) {
                int M = L + e;
                int a = M >> 5, r5 = M & 31;
                Qs2f[(c * 64 + a * 16 + (r5 & 15)) * 2 + (r5 >> 4)] = qa[e];
            }
        }
    }
    __syncthreads();

    const int tx = t & 15, ty = t >> 4;
    u64 acc2[8][4];
#pragma unroll
    for (int i = 0; i < 8; i++)
#pragma unroll
        for (int j = 0; j < 4; j++) acc2[i][j] = 0ull;

#pragma unroll 4
    for (int c = 0; c < QCH; c++) {
        u64 bb[4];
#pragma unroll
        for (int jp = 0; jp < 4; jp++) bb[jp] = Qs2[c * 64 + jp * 16 + tx];
        const ulonglong2* ap2 = (const ulonglong2*)&As2[c * 128 + ty * 8];
        ulonglong2 a01 = ap2[0];
        ulonglong2 a23 = ap2[1];
        ulonglong2 a45 = ap2[2];
        ulonglong2 a67 = ap2[3];
        u64 aa[8] = {a01.x, a01.y, a23.x, a23.y, a45.x, a45.y, a67.x, a67.y};
#pragma unroll
        for (int i = 0; i < 8; i++)
#pragma unroll
            for (int jp = 0; jp < 4; jp++)
                fma2(acc2[i][jp], aa[i], bb[jp]);
    }
    __syncthreads();

#pragma unroll
    for (int i = 0; i < 8; i++) {
        int row = ty * 8 + i;
#pragma unroll
        for (int jp = 0; jp < 4; jp++) {
            int col = jp * 32 + tx;
            Ds[row * 144 + col]      = lo32(acc2[i][jp]);
            Ds[row * 144 + col + 16] = hi32(acc2[i][jp]);
        }
    }
    __syncthreads();

    const int cg = t & 31, rg = t >> 5;
    const int c0 = cg * 4;
    float* Eout = g_E + ((size_t)b * HWSZ + l0) * HWSZ + m0;

#pragma unroll 2
    for (int it = 0; it < 16; it++) {
        int r  = it * 8 + rg;
        int lx = r & 63;
        bool rup = (lx >= 1), rdn = (lx <= 62);
        int rm = rup ? r - 1 : r;
        int rp = rdn ? r + 1 : r;
        const float* Rm = Ds + rm * 144;
        const float* R0 = Ds + r  * 144;
        const float* Rp = Ds + rp * 144;

        float4 mid = *(const float4*)(R0 + c0);
        float4 upA = (c0 > 0)   ? *(const float4*)(Rm + c0 - 4) : make_float4(0,0,0,0);
        float4 upB = *(const float4*)(Rm + c0);
        float4 dnA = *(const float4*)(Rp + c0);
        float4 dnB = (c0 < 124) ? *(const float4*)(Rp + c0 + 4) : make_float4(0,0,0,0);

        float4 res;
        res.x = mid.x + ((rup && (( c0      & 63) != 0 )) ? upA.w : 0.f)
                      + ((rdn && (( c0      & 63) != 63)) ? dnA.y : 0.f);
        res.y = mid.y + ((rup && (((c0 + 1) & 63) != 0 )) ? upB.x : 0.f)
                      + ((rdn && (((c0 + 1) & 63) != 63)) ? dnA.z : 0.f);
        res.z = mid.z + ((rup && (((c0 + 2) & 63) != 0 )) ? upB.y : 0.f)
                      + ((rdn && (((c0 + 2) & 63) != 63)) ? dnA.w : 0.f);
        res.w = mid.w + ((rup && (((c0 + 3) & 63) != 0 )) ? upB.z : 0.f)
                      + ((rdn && (((c0 + 3) & 63) != 63)) ? dnB.x : 0.f);

        *(float4*)(Eout + (size_t)r * HWSZ + c0) = res;
    }
}

// ---------------- phase 2: y-pass + normalize + argmax over l ------------------
__global__ void argmax_kernel() {
    const int b     = blockIdx.y;
    const int m0    = blockIdx.x * 128;
    const int lbase = blockIdx.z * 512;
    const int t     = threadIdx.x;
    const int mg    = t & 31;
    const int lane  = t >> 5;
    const int m     = m0 + mg * 4;

    const float4 invq4 = *(const float4*)(g_invq + b * HWSZ + m);
    const float* Eb = g_E + (size_t)b * HWSZ * HWSZ;
    const float* ik = g_invk + b * HWSZ;

    const bool mup = (m >= 64);
    const bool mdn = (m < HWSZ - 64);

    float bv0 = -2.f, bv1 = -2.f, bv2 = -2.f, bv3 = -2.f;
    int   bl0 = 0,    bl1 = 0,    bl2 = 0,    bl3 = 0;

#pragma unroll 4
    for (int l = lbase + lane; l < lbase + 512; l += 8) {
        const float* row = Eb + (size_t)l * HWSZ + m;
        float4 s = *(const float4*)row;
        float4 a = make_float4(0,0,0,0), c = make_float4(0,0,0,0);
        if (mup && l >= 64)
            a = *(const float4*)(row - 64 * HWSZ - 64);
        if (mdn && l < HWSZ - 64)
            c = *(const float4*)(row + 64 * HWSZ + 64);
        float ikl = ik[l];
        float r0 = (s.x + a.x + c.x) * ikl * invq4.x;
        float r1 = (s.y + a.y + c.y) * ikl * invq4.y;
        float r2 = (s.z + a.z + c.z) * ikl * invq4.z;
        float r3 = (s.w + a.w + c.w) * ikl * invq4.w;
        if (r0 > bv0) { bv0 = r0; bl0 = l; }
        if (r1 > bv1) { bv1 = r1; bl1 = l; }
        if (r2 > bv2) { bv2 = r2; bl2 = l; }
        if (r3 > bv3) { bv3 = r3; bl3 = l; }
    }

    __shared__ u64 sm[128];
    if (t < 128) sm[t] = 0ull;
    __syncthreads();

    atomicMax(&sm[mg * 4 + 0], ((u64)fkey(bv0) << 32) | (unsigned)(~bl0));
    atomicMax(&sm[mg * 4 + 1], ((u64)fkey(bv1) << 32) | (unsigned)(~bl1));
    atomicMax(&sm[mg * 4 + 2], ((u64)fkey(bv2) << 32) | (unsigned)(~bl2));
    atomicMax(&sm[mg * 4 + 3], ((u64)fkey(bv3) << 32) | (unsigned)(~bl3));
    __syncthreads();

    if (t < 128)
        atomicMax(&g_pk[b * HWSZ + m0 + t], sm[t]);
}

// ---------------- gather selected patches, fold, combine -----------------------
__global__ void final_kernel(const float* __restrict__ x, float* __restrict__ out) {
    const int idx = blockIdx.x * 256 + threadIdx.x;
    const int xx = idx & 63;
    const int yy = (idx >> 6) & 63;
    const int c  = (idx >> 12) & 63;
    const int b  = idx >> 18;

    const float* vb = g_v + ((size_t)b * CH + c) * HWSZ;
    const u64* pb = g_pk + (size_t)b * HWSZ;

    float T = 0.f;
#pragma unroll
    for (int i = 0; i < 3; i++) {
#pragma unroll
        for (int j = 0; j < 3; j++) {
            int ny = yy + 1 - i, nx = xx + 1 - j;
            if (ny >= 0 && ny < HH && nx >= 0 && nx < WW) {
                u64 p = pb[ny * WW + nx];
                int l = (int)(~(unsigned)p);
                int ry = l >> 6, rx = l & 63;
                int vy = ry + i - 1, vx = rx + j - 1;
                if (vy >= 0 && vy < HH && vx >= 0 && vx < WW)
                    T += vb[vy * WW + vx];
            }
        }
    }

    u64 pc = pb[yy * WW + xx];
    unsigned key = (unsigned)(pc >> 32);
    unsigned bits = (key & 0x80000000u) ? (key ^ 0x80000000u) : ~key;
    float S = __uint_as_float(bits);

    out[idx] = g_f2[idx] + x[idx] + (T * (1.f / 9.f)) * S;
}

// -------------------------------------------------------------------------------
extern "C" void kernel_launch(void* const* d_in, const int* in_sizes, int n_in,
                              void* d_out, int out_size) {
    const float* x    = (const float*)d_in[0];
    const float* w_f1 = (const float*)d_in[1];
    const float* b_f1 = (const float*)d_in[2];
    const float* w_f2 = (const float*)d_in[3];
    const float* b_f2 = (const float*)d_in[4];
    const float* w_v1 = (const float*)d_in[5];
    const float* b_v1 = (const float*)d_in[6];
    const float* w_v2 = (const float*)d_in[7];
    const float* b_v2 = (const float*)d_in[8];
    const float* w_q  = (const float*)d_in[9];
    const float* b_q  = (const float*)d_in[10];
    const float* w_k  = (const float*)d_in[11];
    const float* b_k  = (const float*)d_in[12];
    float* out = (float*)d_out;

    static cudaStream_t s1 = nullptr;
    static cudaEvent_t evA = nullptr, evN = nullptr, evB = nullptr;
    if (!s1) {
        cudaStreamCreateWithFlags(&s1, cudaStreamNonBlocking);
        cudaEventCreateWithFlags(&evA, cudaEventDisableTiming);
        cudaEventCreateWithFlags(&evN, cudaEventDisableTiming);
        cudaEventCreateWithFlags(&evB, cudaEventDisableTiming);
    }

    cudaFuncSetAttribute(gemmE_kernel,
                         cudaFuncAttributeMaxDynamicSharedMemorySize, 73728);

    dim3 blk(256);

    // main: convA -> gemmE -> (wait norm) argmax -> (wait convB) final
    convA_kernel<<<dim3(8, 12, BATCH), blk>>>(x, w_f1, b_f1, w_v1, b_v1,
                                              w_q, b_q, w_k, b_k);
    cudaEventRecord(evA, 0);

    // side: sqsum -> norm (argmax deps) then convB (final deps)
    cudaStreamWaitEvent(s1, evA, 0);
    sqsum_kernel<<<dim3(16, BATCH), blk, 0, s1>>>();
    norm_kernel<<<dim3(16, BATCH), blk, 0, s1>>>();
    cudaEventRecord(evN, s1);
    convB_kernel<<<dim3(8, 8, BATCH), blk, 0, s1>>>(x, w_v2, b_v2, w_f2, b_f2);
    cudaEventRecord(evB, s1);

    gemmE_kernel<<<dim3(32, 32, BATCH), blk, 73728>>>();
    cudaStreamWaitEvent(0, evN, 0);
    argmax_kernel<<<dim3(32, BATCH, 8), blk>>>();

    cudaStreamWaitEvent(0, evB, 0);
    final_kernel<<<dim3(4096), blk>>>(x, out);
}

// round 15
// speedup vs baseline: 1.3103x; 1.0375x over previous
#include <cuda_runtime.h>

#define HH 64
#define WW 64
#define HWSZ 4096          // 64*64
#define CH 64
#define QCH 32
#define BATCH 4

typedef unsigned long long u64;

// ---------------- scratch (device globals; no allocation allowed) -------------
__device__ float g_v1[BATCH*CH*HWSZ];
__device__ float g_v [BATCH*CH*HWSZ];
__device__ float g_f1[BATCH*CH*HWSZ];
__device__ float g_f2[BATCH*CH*HWSZ];
__device__ float g_q [BATCH*QCH*HWSZ];
__device__ float g_k [BATCH*QCH*HWSZ];
__device__ float g_sqq[BATCH*HWSZ];
__device__ float g_sqk[BATCH*HWSZ];
__device__ float g_invq[BATCH*HWSZ];
__device__ float g_invk[BATCH*HWSZ];
__device__ u64   g_pk[BATCH*HWSZ];                 // packed (fkey(max)<<32)|~argmax
__device__ float g_E[(size_t)BATCH*HWSZ*HWSZ];     // x-pass box-summed dots (fp32)

// ---------------- helpers -----------------------------------------------------
__device__ __forceinline__ unsigned fkey(float f) {
    unsigned u = __float_as_uint(f);
    return (u & 0x80000000u) ? ~u : (u | 0x80000000u);
}
__device__ __forceinline__ u64 pack2(float lo, float hi) {
    u64 r;
    asm("mov.b64 %0, {%1, %2};" : "=l"(r)
        : "r"(__float_as_uint(lo)), "r"(__float_as_uint(hi)));
    return r;
}
__device__ __forceinline__ void fma2(u64 &d, u64 a, u64 b) {
    asm("fma.rn.f32x2 %0, %1, %2, %0;" : "+l"(d) : "l"(a), "l"(b));
}
__device__ __forceinline__ float lo32(u64 v) { return __uint_as_float((unsigned)v); }
__device__ __forceinline__ float hi32(u64 v) { return __uint_as_float((unsigned)(v >> 32)); }
__device__ __forceinline__ u64 u64max_(u64 a, u64 b) { return a > b ? a : b; }

// ---------------- 3x3 same conv body, Cin=64, NCHW, f32x2 ---------------------
// block: 256 threads; spatial tile 32(h) x 16(w); each thread: 2 pixels x 16 oc.
__device__ __forceinline__ void conv_body(const float* __restrict__ in,
                                          const float* __restrict__ in2,
                                          const float* __restrict__ w,
                                          const float* __restrict__ bias,
                                          float* __restrict__ out,
                                          int oc0, int relu, int b, int Cout) {
    __shared__ float tile[16][34][18];   // [ci][y][x] halo tile
    __shared__ u64 ws2[16*9*8];          // [ci][tap][ocpair]

    const int tid = threadIdx.x;
    const int px = tid & 15, py = tid >> 4;
    const int ty0 = (blockIdx.x >> 2) * 32;
    const int tx0 = (blockIdx.x & 3) * 16;

    u64 acc0[8], acc1[8];
#pragma unroll
    for (int o = 0; o < 8; o++) { acc0[o] = 0ull; acc1[o] = 0ull; }

    const float* inb  = in  + (size_t)b * CH * HWSZ;
    const float* in2b = in2 ? in2 + (size_t)b * CH * HWSZ : nullptr;

    for (int c0 = 0; c0 < CH; c0 += 16) {
        for (int idx = tid; idx < 16*34*18; idx += 256) {
            int ci  = idx / 612;
            int rem = idx - ci * 612;
            int yy  = rem / 18, xx = rem - yy * 18;
            int gy = ty0 + yy - 1, gx = tx0 + xx - 1;
            float val = 0.f;
            if (gy >= 0 && gy < HH && gx >= 0 && gx < WW) {
                size_t off = (size_t)(c0 + ci) * HWSZ + gy * WW + gx;
                val = inb[off];
                if (in2b) val += in2b[off];
            }
            tile[ci][yy][xx] = val;
        }
        for (int idx = tid; idx < 16*9*8; idx += 256) {
            int o  = idx & 7;
            int tt = (idx >> 3) % 9;
            int ci = idx / 72;
            float w0 = w[((size_t)(oc0 + 2*o)     * CH + (c0 + ci)) * 9 + tt];
            float w1 = w[((size_t)(oc0 + 2*o + 1) * CH + (c0 + ci)) * 9 + tt];
            ws2[idx] = pack2(w0, w1);
        }
        __syncthreads();

#pragma unroll 2
        for (int ci = 0; ci < 16; ci++) {
#pragma unroll
            for (int t = 0; t < 9; t++) {
                const int dy = t / 3, dx = t - 3 * (t / 3);
                float xv0 = tile[ci][py + dy][px + dx];
                float xv1 = tile[ci][py + 16 + dy][px + dx];
                u64 x02 = pack2(xv0, xv0);
                u64 x12 = pack2(xv1, xv1);
                const u64* wp = &ws2[(ci * 9 + t) * 8];
#pragma unroll
                for (int o = 0; o < 8; o++) {
                    u64 wv = wp[o];
                    fma2(acc0[o], x02, wv);
                    fma2(acc1[o], x12, wv);
                }
            }
        }
        __syncthreads();
    }

    const int gx = tx0 + px;
    const int gy0 = ty0 + py, gy1 = ty0 + py + 16;
#pragma unroll
    for (int o = 0; o < 8; o++) {
        float bia0 = bias[oc0 + 2*o], bia1 = bias[oc0 + 2*o + 1];
        float a0 = lo32(acc0[o]) + bia0;
        float a1 = hi32(acc0[o]) + bia1;
        float b0 = lo32(acc1[o]) + bia0;
        float b1 = hi32(acc1[o]) + bia1;
        if (relu) {
            a0 = fmaxf(a0, 0.f); a1 = fmaxf(a1, 0.f);
            b0 = fmaxf(b0, 0.f); b1 = fmaxf(b1, 0.f);
        }
        size_t o0 = ((size_t)b * Cout + oc0 + 2*o)     * HWSZ;
        size_t o1 = ((size_t)b * Cout + oc0 + 2*o + 1) * HWSZ;
        out[o0 + gy0 * WW + gx] = a0;
        out[o1 + gy0 * WW + gx] = a1;
        out[o0 + gy1 * WW + gx] = b0;
        out[o1 + gy1 * WW + gx] = b1;
    }
}

// q,k convs only (critical path head). y: 0-1 q, 2-3 k
__global__ void __launch_bounds__(256, 3)
convQK_kernel(const float* __restrict__ x,
              const float* __restrict__ w_q, const float* __restrict__ b_q,
              const float* __restrict__ w_k, const float* __restrict__ b_k) {
    int y = blockIdx.y, b = blockIdx.z;
    if (y < 2) conv_body(x, nullptr, w_q, b_q, g_q, y * 16,       0, b, QCH);
    else       conv_body(x, nullptr, w_k, b_k, g_k, (y - 2) * 16, 0, b, QCH);
}

// f1(relu), v1 convs. y: 0-3 f1, 4-7 v1
__global__ void __launch_bounds__(256, 3)
convFV_kernel(const float* __restrict__ x,
              const float* __restrict__ w_f1, const float* __restrict__ b_f1,
              const float* __restrict__ w_v1, const float* __restrict__ b_v1) {
    int y = blockIdx.y, b = blockIdx.z;
    if (y < 4) conv_body(x, nullptr, w_f1, b_f1, g_f1, y * 16,       1, b, CH);
    else       conv_body(x, nullptr, w_v1, b_v1, g_v1, (y - 4) * 16, 0, b, CH);
}

__global__ void __launch_bounds__(256, 3)
convB_kernel(const float* __restrict__ x,
             const float* __restrict__ w_v2, const float* __restrict__ b_v2,
             const float* __restrict__ w_f2, const float* __restrict__ b_f2) {
    int y = blockIdx.y, b = blockIdx.z;
    if (y < 4) conv_body(g_v1, x,       w_v2, b_v2, g_v,  y * 16,       0, b, CH);
    else       conv_body(g_f1, nullptr, w_f2, b_f2, g_f2, (y - 4) * 16, 1, b, CH);
}

// ---------------- per-pixel squared channel sums (grid 16 x B) -----------------
__global__ void sqsum_kernel() {
    int b = blockIdx.y;
    int p = blockIdx.x * 256 + threadIdx.x;
    float sq = 0.f, sk = 0.f;
#pragma unroll 4
    for (int c = 0; c < QCH; c++) {
        float qv = g_q[((size_t)b * QCH + c) * HWSZ + p];
        float kv = g_k[((size_t)b * QCH + c) * HWSZ + p];
        sq += qv * qv;
        sk += kv * kv;
    }
    g_sqq[b * HWSZ + p] = sq;
    g_sqk[b * HWSZ + p] = sk;
}

// masked 3x3 box-sum -> inverse patch norms; also zero g_pk (grid 16 x B)
__global__ void norm_kernel() {
    int b = blockIdx.y;
    int p = blockIdx.x * 256 + threadIdx.x;
    int y = p >> 6, x = p & 63;
    float sq = 0.f, sk = 0.f;
#pragma unroll
    for (int i = -1; i <= 1; i++) {
        int yy = y + i;
        if (yy < 0 || yy >= HH) continue;
#pragma unroll
        for (int j = -1; j <= 1; j++) {
            int xx = x + j;
            if (xx < 0 || xx >= WW) continue;
            int q = b * HWSZ + yy * WW + xx;
            sq += g_sqq[q];
            sk += g_sqk[q];
        }
    }
    g_invq[b * HWSZ + p] = 1.f / fmaxf(sqrtf(sq), 1e-12f);
    g_invk[b * HWSZ + p] = 1.f / fmaxf(sqrtf(sk), 1e-12f);
    g_pk[b * HWSZ + p] = 0ull;
}

// ---------------- phase 1: D tile (K=32 GEMM, f32x2) + fused x-pass -> E -------
__global__ void __launch_bounds__(256, 2) gemmE_kernel() {
    extern __shared__ unsigned char smbuf[];
    u64*   As2  = (u64*)smbuf;                    // [32][128] dup (k,k)
    u64*   Qs2  = (u64*)(smbuf + 32768);          // [32][64] pairs (q_m, q_m+16)
    float* Qs2f = (float*)(smbuf + 32768);
    float* Ds   = (float*)smbuf;                  // [128][144] (after sync)

    const int b  = blockIdx.z;
    const int m0 = blockIdx.x * 128;
    const int l0 = blockIdx.y * 128;
    const int t  = threadIdx.x;

    const float* kb = g_k + (size_t)b * QCH * HWSZ;
    const float* qb = g_q + (size_t)b * QCH * HWSZ;

    {
        int c = t >> 3, sub = t & 7;
        const float* krow = kb + (size_t)c * HWSZ + l0 + sub * 16;
        const float* qrow = qb + (size_t)c * HWSZ + m0 + sub * 16;
#pragma unroll
        for (int g4 = 0; g4 < 4; g4++) {
            float4 kv = *(const float4*)(krow + g4 * 4);
            int L = sub * 16 + g4 * 4;
            As2[c * 128 + L + 0] = pack2(kv.x, kv.x);
            As2[c * 128 + L + 1] = pack2(kv.y, kv.y);
            As2[c * 128 + L + 2] = pack2(kv.z, kv.z);
            As2[c * 128 + L + 3] = pack2(kv.w, kv.w);
            float4 qv = *(const float4*)(qrow + g4 * 4);
            float qa[4] = {qv.x, qv.y, qv.z, qv.w};
#pragma unroll
            for (int e = 0; e < 4; e++) {
                int M = L + e;
                int a = M >> 5, r5 = M & 31;
                Qs2f[(c * 64 + a * 16 + (r5 & 15)) * 2 + (r5 >> 4)] = qa[e];
            }
        }
    }
    __syncthreads();

    const int tx = t & 15, ty = t >> 4;
    u64 acc2[8][4];
#pragma unroll
    for (int i = 0; i < 8; i++)
#pragma unroll
        for (int j = 0; j < 4; j++) acc2[i][j] = 0ull;

#pragma unroll 4
    for (int c = 0; c < QCH; c++) {
        u64 bb[4];
#pragma unroll
        for (int jp = 0; jp < 4; jp++) bb[jp] = Qs2[c * 64 + jp * 16 + tx];
        const ulonglong2* ap2 = (const ulonglong2*)&As2[c * 128 + ty * 8];
        ulonglong2 a01 = ap2[0];
        ulonglong2 a23 = ap2[1];
        ulonglong2 a45 = ap2[2];
        ulonglong2 a67 = ap2[3];
        u64 aa[8] = {a01.x, a01.y, a23.x, a23.y, a45.x, a45.y, a67.x, a67.y};
#pragma unroll
        for (int i = 0; i < 8; i++)
#pragma unroll
            for (int jp = 0; jp < 4; jp++)
                fma2(acc2[i][jp], aa[i], bb[jp]);
    }
    __syncthreads();

#pragma unroll
    for (int i = 0; i < 8; i++) {
        int row = ty * 8 + i;
#pragma unroll
        for (int jp = 0; jp < 4; jp++) {
            int col = jp * 32 + tx;
            Ds[row * 144 + col]      = lo32(acc2[i][jp]);
            Ds[row * 144 + col + 16] = hi32(acc2[i][jp]);
        }
    }
    __syncthreads();

    const int cg = t & 31, rg = t >> 5;
    const int c0 = cg * 4;
    float* Eout = g_E + ((size_t)b * HWSZ + l0) * HWSZ + m0;

#pragma unroll 2
    for (int it = 0; it < 16; it++) {
        int r  = it * 8 + rg;
        int lx = r & 63;
        bool rup = (lx >= 1), rdn = (lx <= 62);
        int rm = rup ? r - 1 : r;
        int rp = rdn ? r + 1 : r;
        const float* Rm = Ds + rm * 144;
        const float* R0 = Ds + r  * 144;
        const float* Rp = Ds + rp * 144;

        float4 mid = *(const float4*)(R0 + c0);
        float4 upA = (c0 > 0)   ? *(const float4*)(Rm + c0 - 4) : make_float4(0,0,0,0);
        float4 upB = *(const float4*)(Rm + c0);
        float4 dnA = *(const float4*)(Rp + c0);
        float4 dnB = (c0 < 124) ? *(const float4*)(Rp + c0 + 4) : make_float4(0,0,0,0);

        float4 res;
        res.x = mid.x + ((rup && (( c0      & 63) != 0 )) ? upA.w : 0.f)
                      + ((rdn && (( c0      & 63) != 63)) ? dnA.y : 0.f);
        res.y = mid.y + ((rup && (((c0 + 1) & 63) != 0 )) ? upB.x : 0.f)
                      + ((rdn && (((c0 + 1) & 63) != 63)) ? dnA.z : 0.f);
        res.z = mid.z + ((rup && (((c0 + 2) & 63) != 0 )) ? upB.y : 0.f)
                      + ((rdn && (((c0 + 2) & 63) != 63)) ? dnA.w : 0.f);
        res.w = mid.w + ((rup && (((c0 + 3) & 63) != 0 )) ? upB.z : 0.f)
                      + ((rdn && (((c0 + 3) & 63) != 63)) ? dnB.x : 0.f);

        *(float4*)(Eout + (size_t)r * HWSZ + c0) = res;
    }
}

// ---------------- phase 2: y-pass + normalize + argmax over l ------------------
__global__ void argmax_kernel() {
    const int b     = blockIdx.y;
    const int m0    = blockIdx.x * 128;
    const int lbase = blockIdx.z * 512;
    const int t     = threadIdx.x;
    const int mg    = t & 31;
    const int lane  = t >> 5;
    const int m     = m0 + mg * 4;

    const float4 invq4 = *(const float4*)(g_invq + b * HWSZ + m);
    const float* Eb = g_E + (size_t)b * HWSZ * HWSZ;
    const float* ik = g_invk + b * HWSZ;

    const bool mup = (m >= 64);
    const bool mdn = (m < HWSZ - 64);

    float bv0 = -2.f, bv1 = -2.f, bv2 = -2.f, bv3 = -2.f;
    int   bl0 = 0,    bl1 = 0,    bl2 = 0,    bl3 = 0;

#pragma unroll 4
    for (int l = lbase + lane; l < lbase + 512; l += 8) {
        const float* row = Eb + (size_t)l * HWSZ + m;
        float4 s = *(const float4*)row;
        float4 a = make_float4(0,0,0,0), c = make_float4(0,0,0,0);
        if (mup && l >= 64)
            a = *(const float4*)(row - 64 * HWSZ - 64);
        if (mdn && l < HWSZ - 64)
            c = *(const float4*)(row + 64 * HWSZ + 64);
        float ikl = ik[l];
        float r0 = (s.x + a.x + c.x) * ikl * invq4.x;
        float r1 = (s.y + a.y + c.y) * ikl * invq4.y;
        float r2 = (s.z + a.z + c.z) * ikl * invq4.z;
        float r3 = (s.w + a.w + c.w) * ikl * invq4.w;
        if (r0 > bv0) { bv0 = r0; bl0 = l; }
        if (r1 > bv1) { bv1 = r1; bl1 = l; }
        if (r2 > bv2) { bv2 = r2; bl2 = l; }
        if (r3 > bv3) { bv3 = r3; bl3 = l; }
    }

    __shared__ u64 sm[128];
    if (t < 128) sm[t] = 0ull;
    __syncthreads();

    atomicMax(&sm[mg * 4 + 0], ((u64)fkey(bv0) << 32) | (unsigned)(~bl0));
    atomicMax(&sm[mg * 4 + 1], ((u64)fkey(bv1) << 32) | (unsigned)(~bl1));
    atomicMax(&sm[mg * 4 + 2], ((u64)fkey(bv2) << 32) | (unsigned)(~bl2));
    atomicMax(&sm[mg * 4 + 3], ((u64)fkey(bv3) << 32) | (unsigned)(~bl3));
    __syncthreads();

    if (t < 128)
        atomicMax(&g_pk[b * HWSZ + m0 + t], sm[t]);
}

// ---------------- gather selected patches, fold, combine -----------------------
__global__ void final_kernel(const float* __restrict__ x, float* __restrict__ out) {
    const int idx = blockIdx.x * 256 + threadIdx.x;
    const int xx = idx & 63;
    const int yy = (idx >> 6) & 63;
    const int c  = (idx >> 12) & 63;
    const int b  = idx >> 18;

    const float* vb = g_v + ((size_t)b * CH + c) * HWSZ;
    const u64* pb = g_pk + (size_t)b * HWSZ;

    float T = 0.f;
#pragma unroll
    for (int i = 0; i < 3; i++) {
#pragma unroll
        for (int j = 0; j < 3; j++) {
            int ny = yy + 1 - i, nx = xx + 1 - j;
            if (ny >= 0 && ny < HH && nx >= 0 && nx < WW) {
                u64 p = pb[ny * WW + nx];
                int l = (int)(~(unsigned)p);
                int ry = l >> 6, rx = l & 63;
                int vy = ry + i - 1, vx = rx + j - 1;
                if (vy >= 0 && vy < HH && vx >= 0 && vx < WW)
                    T += vb[vy * WW + vx];
            }
        }
    }

    u64 pc = pb[yy * WW + xx];
    unsigned key = (unsigned)(pc >> 32);
    unsigned bits = (key & 0x80000000u) ? (key ^ 0x80000000u) : ~key;
    float S = __uint_as_float(bits);

    out[idx] = g_f2[idx] + x[idx] + (T * (1.f / 9.f)) * S;
}

// -------------------------------------------------------------------------------
extern "C" void kernel_launch(void* const* d_in, const int* in_sizes, int n_in,
                              void* d_out, int out_size) {
    const float* x    = (const float*)d_in[0];
    const float* w_f1 = (const float*)d_in[1];
    const float* b_f1 = (const float*)d_in[2];
    const float* w_f2 = (const float*)d_in[3];
    const float* b_f2 = (const float*)d_in[4];
    const float* w_v1 = (const float*)d_in[5];
    const float* b_v1 = (const float*)d_in[6];
    const float* w_v2 = (const float*)d_in[7];
    const float* b_v2 = (const float*)d_in[8];
    const float* w_q  = (const float*)d_in[9];
    const float* b_q  = (const float*)d_in[10];
    const float* w_k  = (const float*)d_in[11];
    const float* b_k  = (const float*)d_in[12];
    float* out = (float*)d_out;

    static cudaStream_t s1 = nullptr, s2 = nullptr;
    static cudaEvent_t evRoot = nullptr, evQK = nullptr, evN = nullptr, evB = nullptr;
    if (!s1) {
        cudaStreamCreateWithFlags(&s1, cudaStreamNonBlocking);
        cudaStreamCreateWithFlags(&s2, cudaStreamNonBlocking);
        cudaEventCreateWithFlags(&evRoot, cudaEventDisableTiming);
        cudaEventCreateWithFlags(&evQK, cudaEventDisableTiming);
        cudaEventCreateWithFlags(&evN, cudaEventDisableTiming);
        cudaEventCreateWithFlags(&evB, cudaEventDisableTiming);
    }

    cudaFuncSetAttribute(gemmE_kernel,
                         cudaFuncAttributeMaxDynamicSharedMemorySize, 73728);

    dim3 blk(256);

    // fork root so side streams enter the capture legally
    cudaEventRecord(evRoot, 0);

    // main: convQK -> gemmE -> (wait norm) argmax -> (wait convB) final
    convQK_kernel<<<dim3(8, 4, BATCH), blk>>>(x, w_q, b_q, w_k, b_k);
    cudaEventRecord(evQK, 0);

    // s1 (forked from root): f1/v1 convs -> convB
    cudaStreamWaitEvent(s1, evRoot, 0);
    convFV_kernel<<<dim3(8, 8, BATCH), blk, 0, s1>>>(x, w_f1, b_f1, w_v1, b_v1);
    convB_kernel<<<dim3(8, 8, BATCH), blk, 0, s1>>>(x, w_v2, b_v2, w_f2, b_f2);
    cudaEventRecord(evB, s1);

    // s2 (forked from QK): norms
    cudaStreamWaitEvent(s2, evQK, 0);
    sqsum_kernel<<<dim3(16, BATCH), blk, 0, s2>>>();
    norm_kernel<<<dim3(16, BATCH), blk, 0, s2>>>();
    cudaEventRecord(evN, s2);

    gemmE_kernel<<<dim3(32, 32, BATCH), blk, 73728>>>();
    cudaStreamWaitEvent(0, evN, 0);
    argmax_kernel<<<dim3(32, BATCH, 8), blk>>>();

    cudaStreamWaitEvent(0, evB, 0);
    final_kernel<<<dim3(4096), blk>>>(x, out);
}